// round 14
// baseline (speedup 1.0000x reference)
#include <cuda_runtime.h>

#define IN_CH 16
#define OUT_CH 64
#define HDIM 32
#define WDIM 32
#define NB 8
#define KHW 9
#define F (IN_CH * KHW)      // 144
#define OCG 8                // out channels per block
#define ROWS 2               // output rows per block
#define NQ 8                 // column quads (4 cols per thread)
#define CSPLIT 8             // input-channel split
#define CPT 2                // channels per thread
#define TPB 128              // 8 quads * 2 rows * 8 cs
#define TW 36                // tile width (16B-aligned rows)
#define PSP 36               // ps inner stride

__device__ __forceinline__ void st4s(float* p, float a, float b, float c, float d) {
    *reinterpret_cast<float4*>(p) = make_float4(a, b, c, d);
}

__global__ __launch_bounds__(TPB, 7) void normdist_kernel(
    const float* __restrict__ x,      // (8,16,32,32)
    const float* __restrict__ weight, // (64,144)
    const float* __restrict__ bias,   // (64)
    float* __restrict__ out)          // (8,64,32,32)
{
    const int og  = blockIdx.x;            // 0..7 out-channel group
    const int rg  = blockIdx.y;            // 0..15 row group
    const int n   = blockIdx.z;            // 0..7 batch
    const int tid = threadIdx.x;
    const int q   = tid & 7;               // 0..7 column quad (cols 4q..4q+3)
    const int r   = (tid >> 3) & 1;        // 0..1 row
    const int cs  = tid >> 4;              // 0..7 channel pair

    const int row0 = rg * ROWS;

    __shared__ __align__(16) float xs[IN_CH][ROWS + 2][TW];   // 9216 B
    __shared__ __align__(16) float wT[F][OCG];                // 4608 B
    __shared__ __align__(16) float ps[4][ROWS][NQ][PSP];      // 9216 B

    if (tid < 64) {
        // ---- x loader: one (c,rr) row per thread, vectorized + shifted store
        const int c  = tid >> 2;           // 0..15
        const int rr = tid & 3;            // 0..3
        const int gr = row0 - 1 + rr;
        float* dst = &xs[c][rr][0];
        if (gr >= 0 && gr < HDIM) {
            const float4* s4 = reinterpret_cast<const float4*>(
                x + ((size_t)n * IN_CH + c) * HDIM * WDIM + gr * WDIM);
            float4 v0 = s4[0], v1 = s4[1], v2 = s4[2], v3 = s4[3];
            float4 v4 = s4[4], v5 = s4[5], v6 = s4[6], v7 = s4[7];
            st4s(dst +  0, 0.0f, v0.x, v0.y, v0.z);
            st4s(dst +  4, v0.w, v1.x, v1.y, v1.z);
            st4s(dst +  8, v1.w, v2.x, v2.y, v2.z);
            st4s(dst + 12, v2.w, v3.x, v3.y, v3.z);
            st4s(dst + 16, v3.w, v4.x, v4.y, v4.z);
            st4s(dst + 20, v4.w, v5.x, v5.y, v5.z);
            st4s(dst + 24, v5.w, v6.x, v6.y, v6.z);
            st4s(dst + 28, v6.w, v7.x, v7.y, v7.z);
            st4s(dst + 32, v7.w, 0.0f, 0.0f, 0.0f);
        } else {
            #pragma unroll
            for (int k = 0; k < 9; k++) st4s(dst + 4 * k, 0.f, 0.f, 0.f, 0.f);
        }
    } else {
        // ---- weight loader: transposed wT[f][oo] = weight[(og*8+oo)*144 + f]
        const int wt = tid - 64;           // 0..63
        const float* wsrc = weight + og * OCG * F;
        #pragma unroll
        for (int k = 0; k < 5; k++) {
            int idx4 = wt + k * 64;        // float4 index, 288 total
            if (idx4 < (F * OCG) / 4) {
                int lin = idx4 * 4;        // oo*144 + f0, f0 % 4 == 0
                int oo  = lin / F;
                int f0  = lin - oo * F;
                float4 v = *reinterpret_cast<const float4*>(wsrc + lin);
                wT[f0 + 0][oo] = v.x;
                wT[f0 + 1][oo] = v.y;
                wT[f0 + 2][oo] = v.z;
                wT[f0 + 3][oo] = v.w;
            }
        }
    }
    __syncthreads();

    // 4 columns x 8 out-channels of accumulators
    float acc[4][OCG];
    #pragma unroll
    for (int k = 0; k < 4; k++)
        #pragma unroll
        for (int o = 0; o < OCG; o++) acc[k][o] = 0.0f;

    const float* x0 = &xs[cs * CPT    ][r][4 * q];
    const float* x1 = &xs[cs * CPT + 1][r][4 * q];
    const float* wbase = &wT[cs * CPT * KHW][0];

    #pragma unroll
    for (int i = 0; i < 3; i++) {
        // 6-wide patch rows for both channels: LDS.128 + LDS.64 each
        float p0[6], p1[6];
        {
            float4 a4 = *reinterpret_cast<const float4*>(x0 + i * TW);
            float2 a2 = *reinterpret_cast<const float2*>(x0 + i * TW + 4);
            p0[0] = a4.x; p0[1] = a4.y; p0[2] = a4.z; p0[3] = a4.w;
            p0[4] = a2.x; p0[5] = a2.y;
            float4 b4 = *reinterpret_cast<const float4*>(x1 + i * TW);
            float2 b2 = *reinterpret_cast<const float2*>(x1 + i * TW + 4);
            p1[0] = b4.x; p1[1] = b4.y; p1[2] = b4.z; p1[3] = b4.w;
            p1[4] = b2.x; p1[5] = b2.y;
        }

        #pragma unroll
        for (int j = 0; j < 3; j++) {
            const float4* w0p = reinterpret_cast<const float4*>(
                wbase + (i * 3 + j) * OCG);
            const float4* w1p = reinterpret_cast<const float4*>(
                wbase + (KHW + i * 3 + j) * OCG);
            float4 wa0 = w0p[0], wb0 = w0p[1];
            float4 wa1 = w1p[0], wb1 = w1p[1];
            const float w0[OCG] = {wa0.x, wa0.y, wa0.z, wa0.w,
                                   wb0.x, wb0.y, wb0.z, wb0.w};
            const float w1[OCG] = {wa1.x, wa1.y, wa1.z, wa1.w,
                                   wb1.x, wb1.y, wb1.z, wb1.w};

            #pragma unroll
            for (int k = 0; k < 4; k++) {
                const float pa = p0[j + k];
                const float pb = p1[j + k];
                #pragma unroll
                for (int o = 0; o < OCG; o++) {
                    acc[k][o] = fmaxf(fmaxf(acc[k][o], fabsf(pa - w0[o])),
                                      fabsf(pb - w1[o]));
                }
            }
        }
    }

    // ---- tree reduction of the 8 channel-pairs
    // stage 1: cs 4..7 write set (cs-4)
    if (cs >= 4) {
        float* p = &ps[cs - 4][r][q][0];
        #pragma unroll
        for (int k = 0; k < 4; k++) {
            st4s(p + k * 8,     acc[k][0], acc[k][1], acc[k][2], acc[k][3]);
            st4s(p + k * 8 + 4, acc[k][4], acc[k][5], acc[k][6], acc[k][7]);
        }
    }
    __syncthreads();

    if (cs < 4) {
        // fold set cs into local acc
        const float* p = &ps[cs][r][q][0];
        #pragma unroll
        for (int k = 0; k < 4; k++) {
            float4 v4  = *reinterpret_cast<const float4*>(p + k * 8);
            float4 v4b = *reinterpret_cast<const float4*>(p + k * 8 + 4);
            acc[k][0] = fmaxf(acc[k][0], v4.x);
            acc[k][1] = fmaxf(acc[k][1], v4.y);
            acc[k][2] = fmaxf(acc[k][2], v4.z);
            acc[k][3] = fmaxf(acc[k][3], v4.w);
            acc[k][4] = fmaxf(acc[k][4], v4b.x);
            acc[k][5] = fmaxf(acc[k][5], v4b.y);
            acc[k][6] = fmaxf(acc[k][6], v4b.z);
            acc[k][7] = fmaxf(acc[k][7], v4b.w);
        }
    }
    __syncthreads();

    // stage 2: cs 1..3 write folded sets
    if (cs >= 1 && cs < 4) {
        float* p = &ps[cs][r][q][0];
        #pragma unroll
        for (int k = 0; k < 4; k++) {
            st4s(p + k * 8,     acc[k][0], acc[k][1], acc[k][2], acc[k][3]);
            st4s(p + k * 8 + 4, acc[k][4], acc[k][5], acc[k][6], acc[k][7]);
        }
    }
    __syncthreads();

    if (cs == 0) {
        // fold 3 remaining sets + write
        #pragma unroll
        for (int g = 1; g < 4; g++) {
            const float* p = &ps[g][r][q][0];
            #pragma unroll
            for (int k = 0; k < 4; k++) {
                float4 v4  = *reinterpret_cast<const float4*>(p + k * 8);
                float4 v4b = *reinterpret_cast<const float4*>(p + k * 8 + 4);
                acc[k][0] = fmaxf(acc[k][0], v4.x);
                acc[k][1] = fmaxf(acc[k][1], v4.y);
                acc[k][2] = fmaxf(acc[k][2], v4.z);
                acc[k][3] = fmaxf(acc[k][3], v4.w);
                acc[k][4] = fmaxf(acc[k][4], v4b.x);
                acc[k][5] = fmaxf(acc[k][5], v4b.y);
                acc[k][6] = fmaxf(acc[k][6], v4b.z);
                acc[k][7] = fmaxf(acc[k][7], v4b.w);
            }
        }

        const float4* b4 = reinterpret_cast<const float4*>(bias + og * OCG);
        float4 bi0 = b4[0], bi1 = b4[1];
        const float bv[OCG] = {bi0.x, bi0.y, bi0.z, bi0.w,
                               bi1.x, bi1.y, bi1.z, bi1.w};

        const int orow = row0 + r;
        float* outp = out + (((size_t)n * OUT_CH + og * OCG) * HDIM + orow) * WDIM + 4 * q;
        #pragma unroll
        for (int o = 0; o < OCG; o++) {
            float4 res = make_float4(acc[0][o] + bv[o], acc[1][o] + bv[o],
                                     acc[2][o] + bv[o], acc[3][o] + bv[o]);
            *reinterpret_cast<float4*>(outp + (size_t)o * HDIM * WDIM) = res;
        }
    }
}

extern "C" void kernel_launch(void* const* d_in, const int* in_sizes, int n_in,
                              void* d_out, int out_size) {
    const float* x      = (const float*)d_in[0];
    const float* weight = (const float*)d_in[1];
    const float* bias   = (const float*)d_in[2];
    float* out          = (float*)d_out;

    dim3 grid(OUT_CH / OCG, HDIM / ROWS, NB);   // (8, 16, 8) = 1024 blocks
    normdist_kernel<<<grid, TPB>>>(x, weight, bias, out);
}